// round 1
// baseline (speedup 1.0000x reference)
#include <cuda_runtime.h>
#include <math.h>

#define NMOL   32
#define NATOM  128
#define DEG    32
#define NTOT   4096
#define NPAIR  131072
#define NSENS  20
#define NIN0   5
#define NF0    40
#define NF1    20
#define NG     80
#define TM     32          // atoms per k_gates block
#define ETS    36          // padded envT row stride (conflict-free, float4-aligned)

// ---------------- scratch (device globals; no allocation) ----------------
__device__ float g_sense[NPAIR * NSENS];   // [pair][s]
__device__ float g_indf [NTOT * NIN0];     // [atom][5]
__device__ float g_xcat [NTOT * 40];       // [atom][0..19]=x_t, [20..39]=h (gather source)
__device__ float g_ct   [NTOT * NF1];
__device__ float g_hbuf [NTOT * NF1];      // h written here (double buffer vs g_xcat)
__device__ float g_x0   [NTOT];

__device__ __forceinline__ float softplusf(float x) {
    return fmaxf(x, 0.f) + log1pf(expf(-fabsf(x)));
}
__device__ __forceinline__ float sigmoidf(float x) {
    return 1.f / (1.f + expf(-x));
}

// ---------------- one-time prep ----------------
__global__ void k_indf(const int* __restrict__ species, const float* __restrict__ x_h) {
    int n = blockIdx.x * blockDim.x + threadIdx.x;
    if (n >= NTOT) return;
    int sp = species[n];
    g_indf[n * 5 + 0] = (sp == 1) ? 1.f : 0.f;
    g_indf[n * 5 + 1] = (sp == 8) ? 1.f : 0.f;
    g_indf[n * 5 + 2] = x_h[n * 3 + 0];
    g_indf[n * 5 + 3] = x_h[n * 3 + 1];
    g_indf[n * 5 + 4] = x_h[n * 3 + 2];
}

__global__ void k_sense(const float* __restrict__ coord, const int* __restrict__ ps) {
    int p = blockIdx.x * blockDim.x + threadIdx.x;
    if (p >= NPAIR) return;
    int a = p >> 5;
    int b = ps[p];
    float dx = coord[a * 3 + 0] - coord[b * 3 + 0];
    float dy = coord[a * 3 + 1] - coord[b * 3 + 1];
    float dz = coord[a * 3 + 2] - coord[b * 3 + 2];
    float d = sqrtf(dx * dx + dy * dy + dz * dz + 1e-12f);
    float cut = 0.f;
    if (d < 7.5f) { float c = cospif(d * (1.f / 15.f)); cut = c * c; }
    float invd = 1.f / d;
    const float m0 = 0.2f;
    const float m1 = 1.f / 0.7f;
    const float dmu = (m1 - m0) / 19.f;
    const float invsig = 20.f / (m1 - m0);
#pragma unroll
    for (int s = 0; s < NSENS; s++) {
        float z = (invd - (m0 + s * dmu)) * invsig;
        g_sense[p * NSENS + s] = expf(-0.5f * z * z) * cut;
    }
}

// ---------------- f0 hipnn (runs once): writes c_t, h_buf ----------------
__global__ void k_f0(const int* __restrict__ ps,
                     const float* __restrict__ iw, const float* __restrict__ sw,
                     const float* __restrict__ sb, const float* __restrict__ aw,
                     const float* __restrict__ ab) {
    __shared__ float ss[32 * 20];
    __shared__ float sX[32 * 5];
    __shared__ float senv[100];
    __shared__ float sy[40];
    __shared__ float sx[5];
    int a = blockIdx.x;
    int t = threadIdx.x;  // 64 threads

    for (int i = t; i < 640; i += 64) ss[i] = g_sense[a * 640 + i];
    if (t < 32) {
        int nb = ps[a * 32 + t];
#pragma unroll
        for (int f = 0; f < 5; f++) sX[t * 5 + f] = g_indf[nb * 5 + f];
    }
    if (t < 5) sx[t] = g_indf[a * 5 + t];
    __syncthreads();

    for (int e = t; e < 100; e += 64) {
        int s = e / 5, f = e % 5;
        float acc = 0.f;
        for (int k = 0; k < 32; k++) acc += ss[k * 20 + s] * sX[k * 5 + f];
        senv[e] = acc;
    }
    __syncthreads();

    if (t < 40) {
        float pre = sb[t];
        for (int e = 0; e < 100; e++) pre += senv[e] * iw[e * 40 + t];
#pragma unroll
        for (int f = 0; f < 5; f++) pre += sx[f] * sw[f * 40 + t];
        sy[t] = softplusf(pre);
    }
    __syncthreads();

    for (int l = 0; l < 3; l++) {
        float v = 0.f;
        if (t < 40) {
            v = ab[l * 40 + t];
            for (int j = 0; j < 40; j++) v += sy[j] * aw[(l * 40 + j) * 40 + t];
            v = softplusf(v);
        }
        __syncthreads();
        if (t < 40) sy[t] = v;
        __syncthreads();
    }
    if (t < 20) {
        g_ct[a * 20 + t]   = sy[t];
        g_hbuf[a * 20 + t] = sy[20 + t];
    }
}

// ---------------- per-step x_t (h1 hipnn), 1 warp per atom ----------------
// mode 0/1: x_in = x_raw[:,mode]; mode 2: x_in = g_x0
// Also copies h_buf -> g_xcat h-slot (so gates gather concat(x_t, h_old) race-free).
__global__ void k_xt(const int* __restrict__ ps, const float* __restrict__ x_raw, int mode,
                     const float* __restrict__ iw, const float* __restrict__ sw,
                     const float* __restrict__ sb, const float* __restrict__ aw,
                     const float* __restrict__ ab) {
    __shared__ float sxin[32];
    __shared__ float se[20];
    __shared__ float sy[20];
    int a = blockIdx.x;
    int t = threadIdx.x;  // 32 threads

    int nb = ps[a * 32 + t];
    sxin[t] = (mode < 2) ? x_raw[nb * 2 + mode] : g_x0[nb];
    float xo = (mode < 2) ? x_raw[a * 2 + mode] : g_x0[a];
    __syncwarp();

    if (t < 20) {
        float acc = 0.f;
        for (int k = 0; k < 32; k++) acc += g_sense[(a * 32 + k) * 20 + t] * sxin[k];
        se[t] = acc;
    }
    __syncwarp();
    if (t < 20) {
        float pre = sb[t] + xo * sw[t];
#pragma unroll
        for (int s = 0; s < 20; s++) pre += se[s] * iw[s * 20 + t];
        sy[t] = softplusf(pre);
    }
    __syncwarp();
    for (int l = 0; l < 3; l++) {
        float v = 0.f;
        if (t < 20) {
            v = ab[l * 20 + t];
#pragma unroll
            for (int j = 0; j < 20; j++) v += sy[j] * aw[(l * 20 + j) * 20 + t];
            v = softplusf(v);
        }
        __syncwarp();
        if (t < 20) sy[t] = v;
        __syncwarp();
    }
    if (t < 20) {
        g_xcat[a * 40 + t]      = sy[t];            // x_t
        g_xcat[a * 40 + 20 + t] = g_hbuf[a * 20 + t]; // h_old into gather buffer
    }
}

// ---------------- per-step W-interact + gates + x0 ----------------
// SMEM layout (floats): xcat[5120] | envT[800*36=28800] | work[20480] | nb[1024 ints]
// work region: sense tile (20480) during env; then Wchunk[0..10239], tmp[10240..12799], o[12800..13439]
#define SMEM_FLOATS (5120 + 28800 + 20480 + 1024)
#define SMEM_BYTES  (SMEM_FLOATS * 4)

__global__ void __launch_bounds__(256, 1)
k_gates(const int* __restrict__ ps,
        const float* __restrict__ Wint, const float* __restrict__ Wself,
        const float* __restrict__ Wb,
        const float* __restrict__ pw0, const float* __restrict__ pw1,
        const float* __restrict__ pb1,
        int outcol, float* __restrict__ out) {
    extern __shared__ float sm[];
    float* s_xcat  = sm;                       // 5120
    float* s_envT  = sm + 5120;                // 28800
    float* s_work  = sm + 5120 + 28800;        // 20480 (sense, then W/tmp/o)
    int*   s_nb    = (int*)(sm + 5120 + 28800 + 20480); // 1024
    float* s_wc    = s_work;                   // 10240
    float* s_tmp   = s_work + 10240;           // 2560
    float* s_o     = s_work + 12800;           // 640

    int t  = threadIdx.x;
    int A0 = blockIdx.x * TM;
    int MB = (A0 / NATOM) * NATOM;
    int L0 = A0 - MB;

    // stage molecule xcat (5120 f), neighbor local idx, tile sense (20480 f)
    {
        const float4* src = (const float4*)(g_xcat + MB * 40);
        float4* dst = (float4*)s_xcat;
        for (int i = t; i < 1280; i += 256) dst[i] = src[i];
        for (int i = t; i < 1024; i += 256) s_nb[i] = ps[A0 * 32 + i] - MB;
        const float4* ssrc = (const float4*)(g_sense + A0 * 640);
        float4* sdst = (float4*)s_work;
        for (int i = t; i < 5120; i += 256) sdst[i] = ssrc[i];
    }
    __syncthreads();

    // env: 32 atoms x 8 threads; each thread: all 20 s x 5 f -> 100 accumulators
    {
        int i  = t >> 3;
        int f0 = (t & 7) * 5;
        float acc[20][5];
#pragma unroll
        for (int s = 0; s < 20; s++)
#pragma unroll
            for (int j = 0; j < 5; j++) acc[s][j] = 0.f;
        const float* sen = s_work + i * 640;
        const int* nbp = s_nb + i * 32;
        for (int k = 0; k < 32; k++) {
            int nb = nbp[k];
            const float* xr = s_xcat + nb * 40 + f0;
            float x0v = xr[0], x1v = xr[1], x2v = xr[2], x3v = xr[3], x4v = xr[4];
            const float* sk = sen + k * 20;
#pragma unroll
            for (int s = 0; s < 20; s++) {
                float sv = sk[s];
                acc[s][0] += sv * x0v;
                acc[s][1] += sv * x1v;
                acc[s][2] += sv * x2v;
                acc[s][3] += sv * x3v;
                acc[s][4] += sv * x4v;
            }
        }
#pragma unroll
        for (int s = 0; s < 20; s++)
#pragma unroll
            for (int j = 0; j < 5; j++)
                s_envT[(s * 40 + f0 + j) * ETS + i] = acc[s][j];
    }

    // GEMM (32x80) = envT(32x800) @ Wint(800x80), 160 active threads, 4x4 tiles
    float a00=0,a01=0,a02=0,a03=0, a10=0,a11=0,a12=0,a13=0,
          a20=0,a21=0,a22=0,a23=0, a30=0,a31=0,a32=0,a33=0;
    bool active = (t < 160);
    int i0 = active ? (t / 20) * 4 : 0;
    int g0 = active ? (t % 20) * 4 : 0;

    for (int e0 = 0; e0 < 800; e0 += 128) {
        int elen = min(128, 800 - e0);
        __syncthreads();  // first iter: env STS done; later: prev chunk consumed
        {
            const float4* wsrc = (const float4*)(Wint + e0 * 80);
            float4* wdst = (float4*)s_wc;
            int n4 = elen * 20;
            for (int i = t; i < n4; i += 256) wdst[i] = wsrc[i];
        }
        __syncthreads();
        if (active) {
            for (int e = 0; e < elen; e++) {
                float4 ev = *(const float4*)&s_envT[(e0 + e) * ETS + i0];
                float4 wv = *(const float4*)&s_wc[e * 80 + g0];
                a00 += ev.x * wv.x; a01 += ev.x * wv.y; a02 += ev.x * wv.z; a03 += ev.x * wv.w;
                a10 += ev.y * wv.x; a11 += ev.y * wv.y; a12 += ev.y * wv.z; a13 += ev.y * wv.w;
                a20 += ev.z * wv.x; a21 += ev.z * wv.y; a22 += ev.z * wv.z; a23 += ev.z * wv.w;
                a30 += ev.w * wv.x; a31 += ev.w * wv.y; a32 += ev.w * wv.z; a33 += ev.w * wv.w;
            }
        }
    }

    if (active) {
        float4 bv = *(const float4*)&Wb[g0];
        a00 += bv.x; a01 += bv.y; a02 += bv.z; a03 += bv.w;
        a10 += bv.x; a11 += bv.y; a12 += bv.z; a13 += bv.w;
        a20 += bv.x; a21 += bv.y; a22 += bv.z; a23 += bv.w;
        a30 += bv.x; a31 += bv.y; a32 += bv.z; a33 += bv.w;
        const float* xc0 = s_xcat + (L0 + i0 + 0) * 40;
        const float* xc1 = s_xcat + (L0 + i0 + 1) * 40;
        const float* xc2 = s_xcat + (L0 + i0 + 2) * 40;
        const float* xc3 = s_xcat + (L0 + i0 + 3) * 40;
#pragma unroll
        for (int f = 0; f < 40; f++) {
            float4 wv = *(const float4*)&Wself[f * 80 + g0];
            float x0v = xc0[f], x1v = xc1[f], x2v = xc2[f], x3v = xc3[f];
            a00 += x0v * wv.x; a01 += x0v * wv.y; a02 += x0v * wv.z; a03 += x0v * wv.w;
            a10 += x1v * wv.x; a11 += x1v * wv.y; a12 += x1v * wv.z; a13 += x1v * wv.w;
            a20 += x2v * wv.x; a21 += x2v * wv.y; a22 += x2v * wv.z; a23 += x2v * wv.w;
            a30 += x3v * wv.x; a31 += x3v * wv.y; a32 += x3v * wv.z; a33 += x3v * wv.w;
        }
        float* d0 = &s_tmp[(i0 + 0) * 80 + g0];
        float* d1 = &s_tmp[(i0 + 1) * 80 + g0];
        float* d2 = &s_tmp[(i0 + 2) * 80 + g0];
        float* d3 = &s_tmp[(i0 + 3) * 80 + g0];
        d0[0]=a00; d0[1]=a01; d0[2]=a02; d0[3]=a03;
        d1[0]=a10; d1[1]=a11; d1[2]=a12; d1[3]=a13;
        d2[0]=a20; d2[1]=a21; d2[2]=a22; d2[3]=a23;
        d3[0]=a30; d3[1]=a31; d3[2]=a32; d3[3]=a33;
    }
    __syncthreads();

    // gates: 640 (atom, j) entries
    for (int idx = t; idx < TM * 20; idx += 256) {
        int i = idx / 20, j = idx % 20;
        int a = A0 + i;
        float t0v = s_tmp[i * 80 + j * 4 + 0];
        float t1v = s_tmp[i * 80 + j * 4 + 1];
        float t2v = s_tmp[i * 80 + j * 4 + 2];
        float t3v = s_tmp[i * 80 + j * 4 + 3];
        float o  = sigmoidf(t3v);
        float cn = sigmoidf(t1v) * g_ct[a * 20 + j] + sigmoidf(t0v) * tanhf(t2v);
        g_ct[a * 20 + j]   = cn;
        g_hbuf[a * 20 + j] = o * tanhf(cn);
        s_o[i * 20 + j] = o;
    }
    __syncthreads();

    // x0 epilogue + optional output column
    if (t < TM) {
        int a = A0 + t;
        float x0v = pb1[0];
#pragma unroll
        for (int f = 0; f < 5; f++)  x0v += g_indf[a * 5 + f] * pw0[f];
#pragma unroll
        for (int j = 0; j < 20; j++) x0v += s_o[t * 20 + j] * pw1[j];
        g_x0[a] = x0v;
        if (outcol >= 0) out[a * 3 + outcol] = x0v;
    }
}

// ---------------- host ----------------
extern "C" void kernel_launch(void* const* d_in, const int* in_sizes, int n_in,
                              void* d_out, int out_size) {
    const int*   species = (const int*)d_in[0];
    const float* coords  = (const float*)d_in[1];
    const float* x_h     = (const float*)d_in[2];
    const float* x_raw   = (const float*)d_in[3];
    const int*   ps      = (const int*)d_in[5];
    const float* h0_iw   = (const float*)d_in[6];
    const float* h0_sw   = (const float*)d_in[7];
    const float* h0_sb   = (const float*)d_in[8];
    const float* h0_aw   = (const float*)d_in[9];
    const float* h0_ab   = (const float*)d_in[10];
    const float* h1_iw   = (const float*)d_in[11];
    const float* h1_sw   = (const float*)d_in[12];
    const float* h1_sb   = (const float*)d_in[13];
    const float* h1_aw   = (const float*)d_in[14];
    const float* h1_ab   = (const float*)d_in[15];
    const float* W_iw    = (const float*)d_in[16];
    const float* W_sw    = (const float*)d_in[17];
    const float* W_sb    = (const float*)d_in[18];
    const float* pw0     = (const float*)d_in[19];
    const float* pw1     = (const float*)d_in[20];
    const float* pb1     = (const float*)d_in[21];
    float* out = (float*)d_out;

    cudaFuncSetAttribute(k_gates, cudaFuncAttributeMaxDynamicSharedMemorySize, SMEM_BYTES);

    k_indf<<<(NTOT + 255) / 256, 256>>>(species, x_h);
    k_sense<<<NPAIR / 256, 256>>>(coords, ps);
    k_f0<<<NTOT, 64>>>(ps, h0_iw, h0_sw, h0_sb, h0_aw, h0_ab);

    for (int s = 0; s < 5; s++) {
        int mode = (s < 2) ? s : 2;
        int outcol = (s >= 2) ? (s - 2) : -1;
        k_xt<<<NTOT, 32>>>(ps, x_raw, mode, h1_iw, h1_sw, h1_sb, h1_aw, h1_ab);
        k_gates<<<NTOT / TM, 256, SMEM_BYTES>>>(ps, W_iw, W_sw, W_sb,
                                                pw0, pw1, pb1, outcol, out);
    }
}